// round 3
// baseline (speedup 1.0000x reference)
#include <cuda_runtime.h>
#include <cstdint>

#define BATCH 4
#define NPTS  4096
#define FIN   64
#define FOUT  64
#define KNN   20
#define TOTAL (BATCH * NPTS)   // 16384 points

// ---------------- scratch (static device memory; no allocations) ----------------
__device__ float g_key[(size_t)TOTAL * NPTS];   // 268 MB ranking keys
__device__ float g_u[TOTAL * FOUT];             // (W1-W2)x + b
__device__ float g_v[TOTAL * FOUT];             // W2 x
__device__ float g_xs[TOTAL];                   // squared norms
__device__ int   g_idx[TOTAL * KNN];            // knn indices (local to batch)

// ---------------- kernel A: per-point transform ----------------
// u = (W1 - W2) x + b ; v = W2 x ; xs = ||x||^2
__global__ void transform_kernel(const float* __restrict__ x,
                                 const float* __restrict__ W,
                                 const float* __restrict__ bias) {
    __shared__ float Ws[FOUT * 2 * FIN];
    __shared__ float bs[FOUT];
    int t = threadIdx.x;
    for (int i = t; i < FOUT * 2 * FIN; i += blockDim.x) Ws[i] = W[i];
    if (t < FOUT) bs[t] = bias[t];
    __syncthreads();

    int p = blockIdx.x * blockDim.x + t;   // grid covers exactly TOTAL
    float xr[FIN];
    const float4* xp = (const float4*)(x + (size_t)p * FIN);
#pragma unroll
    for (int q = 0; q < FIN / 4; q++) {
        float4 v4 = xp[q];
        xr[4*q+0] = v4.x; xr[4*q+1] = v4.y; xr[4*q+2] = v4.z; xr[4*q+3] = v4.w;
    }
    float s = 0.f;
#pragma unroll
    for (int c = 0; c < FIN; c++) s += xr[c] * xr[c];
    g_xs[p] = s;

    for (int o = 0; o < FOUT; o++) {
        float a1 = 0.f, a2 = 0.f;
        const float* wrow = &Ws[o * 2 * FIN];
#pragma unroll
        for (int c = 0; c < FIN; c++) {
            a1 += xr[c] * wrow[c];
            a2 += xr[c] * wrow[FIN + c];
        }
        g_u[p * FOUT + o] = a1 - a2 + bs[o];
        g_v[p * FOUT + o] = a2;
    }
}

// ---------------- kernel B: symmetric Gram + ranking keys ----------------
// key[i][j] = xs[j] - 2*dot(x_i,x_j)   (same row-order as reference dist)
#define TILE 128
#define KCH  32
#define SSTR 132   // padded stride to dodge bank conflicts on transposed stores

__global__ __launch_bounds__(256, 2) void dist_kernel(const float* __restrict__ x) {
    __shared__ float As[KCH][SSTR];
    __shared__ float Bs[KCH][SSTR];
    int b = blockIdx.z;
    // map linear id -> upper-triangular (by, bx), bx >= by, 32x32 tile grid
    int id = blockIdx.x;
    int by = 0, rem = id;
    while (rem >= 32 - by) { rem -= 32 - by; by++; }
    int bx = by + rem;

    const float* X = x + (size_t)b * NPTS * FIN;
    int row0 = by * TILE, col0 = bx * TILE;
    int t  = threadIdx.x;
    int tr = t >> 4, tc = t & 15;          // 16 x 16 thread grid, 8x8 micro-tile

    float acc[8][8];
#pragma unroll
    for (int i = 0; i < 8; i++)
#pragma unroll
        for (int j = 0; j < 8; j++) acc[i][j] = 0.f;

    for (int kk = 0; kk < FIN; kk += KCH) {
        // load 128 rows x 32 f, transposed into f-major smem
        for (int q = t; q < TILE * KCH / 4; q += 256) {
            int r  = q >> 3;
            int fs = (q & 7) << 2;
            float4 va = *(const float4*)(X + (size_t)(row0 + r) * FIN + kk + fs);
            As[fs+0][r] = va.x; As[fs+1][r] = va.y; As[fs+2][r] = va.z; As[fs+3][r] = va.w;
            float4 vb = *(const float4*)(X + (size_t)(col0 + r) * FIN + kk + fs);
            Bs[fs+0][r] = vb.x; Bs[fs+1][r] = vb.y; Bs[fs+2][r] = vb.z; Bs[fs+3][r] = vb.w;
        }
        __syncthreads();
#pragma unroll
        for (int f = 0; f < KCH; f++) {
            float4 a0 = *(const float4*)&As[f][tr * 8];
            float4 a1 = *(const float4*)&As[f][tr * 8 + 4];
            float4 b0 = *(const float4*)&Bs[f][tc * 8];
            float4 b1 = *(const float4*)&Bs[f][tc * 8 + 4];
            float av[8] = {a0.x,a0.y,a0.z,a0.w,a1.x,a1.y,a1.z,a1.w};
            float bv[8] = {b0.x,b0.y,b0.z,b0.w,b1.x,b1.y,b1.z,b1.w};
#pragma unroll
            for (int i = 0; i < 8; i++)
#pragma unroll
                for (int j = 0; j < 8; j++) acc[i][j] += av[i] * bv[j];
        }
        __syncthreads();
    }

    float xsr[8], xsc[8];
#pragma unroll
    for (int i = 0; i < 8; i++) xsr[i] = g_xs[b * NPTS + row0 + tr * 8 + i];
#pragma unroll
    for (int j = 0; j < 8; j++) xsc[j] = g_xs[b * NPTS + col0 + tc * 8 + j];

    // direct block: key[row][col] = xs[col] - 2*acc
#pragma unroll
    for (int i = 0; i < 8; i++) {
        size_t base = (size_t)(b * NPTS + row0 + tr * 8 + i) * NPTS + col0 + tc * 8;
        float4 o0 = make_float4(xsc[0] - 2.f*acc[i][0], xsc[1] - 2.f*acc[i][1],
                                xsc[2] - 2.f*acc[i][2], xsc[3] - 2.f*acc[i][3]);
        float4 o1 = make_float4(xsc[4] - 2.f*acc[i][4], xsc[5] - 2.f*acc[i][5],
                                xsc[6] - 2.f*acc[i][6], xsc[7] - 2.f*acc[i][7]);
        *(float4*)&g_key[base]     = o0;
        *(float4*)&g_key[base + 4] = o1;
    }
    // mirrored block: key[col][row] = xs[row] - 2*acc  (diag tile already full)
    if (bx != by) {
#pragma unroll
        for (int j = 0; j < 8; j++) {
            size_t base = (size_t)(b * NPTS + col0 + tc * 8 + j) * NPTS + row0 + tr * 8;
            float4 o0 = make_float4(xsr[0] - 2.f*acc[0][j], xsr[1] - 2.f*acc[1][j],
                                    xsr[2] - 2.f*acc[2][j], xsr[3] - 2.f*acc[3][j]);
            float4 o1 = make_float4(xsr[4] - 2.f*acc[4][j], xsr[5] - 2.f*acc[5][j],
                                    xsr[6] - 2.f*acc[6][j], xsr[7] - 2.f*acc[7][j]);
            *(float4*)&g_key[base]     = o0;
            *(float4*)&g_key[base + 4] = o1;
        }
    }
}

// ---------------- kernel C: per-row top-20 selection ----------------
// key packed as (ordered float bits << 32) | j  => lexicographic (dist, index),
// exactly matching stable argsort tie-breaks. Self (j==i) excluded.
__global__ void select_kernel() {
    int row = blockIdx.x;
    int iLocal = row & (NPTS - 1);
    const float* keys = g_key + (size_t)row * NPTS;
    int t = threadIdx.x;

    unsigned long long lk[16];
#pragma unroll
    for (int q = 0; q < 16; q++) {
        int j = t + q * 256;
        unsigned u = __float_as_uint(keys[j]);
        u = (u & 0x80000000u) ? ~u : (u | 0x80000000u);
        unsigned long long key = ((unsigned long long)u << 32) | (unsigned)j;
        lk[q] = (j == iLocal) ? ~0ULL : key;
    }

    __shared__ unsigned long long wmin[8];
    int lane = t & 31, wid = t >> 5;
    for (int sel = 0; sel < KNN; sel++) {
        unsigned long long m = ~0ULL;
#pragma unroll
        for (int q = 0; q < 16; q++) m = (lk[q] < m) ? lk[q] : m;
        unsigned long long wm = m;
#pragma unroll
        for (int off = 16; off; off >>= 1) {
            unsigned long long o = __shfl_down_sync(0xffffffffu, wm, off);
            wm = (o < wm) ? o : wm;
        }
        if (lane == 0) wmin[wid] = wm;
        __syncthreads();
        unsigned long long bm = wmin[0];
#pragma unroll
        for (int w = 1; w < 8; w++) bm = (wmin[w] < bm) ? wmin[w] : bm;
        if (m == bm)  // unique owner (index bits make keys unique)
            g_idx[row * KNN + sel] = (int)(bm & 0xffffffffu);
#pragma unroll
        for (int q = 0; q < 16; q++) if (lk[q] == bm) lk[q] = ~0ULL;
        __syncthreads();
    }
}

// ---------------- kernel D: gather-max epilogue ----------------
__global__ void gather_kernel(float* __restrict__ out) {
    int gid = blockIdx.x * blockDim.x + threadIdx.x;   // TOTAL*FOUT threads
    int p = gid >> 6;
    int o = gid & 63;
    int bbase = p & ~(NPTS - 1);
    const int* ip = g_idx + p * KNN;
    float m = -3.402823466e38f;
#pragma unroll
    for (int q = 0; q < KNN; q++) {
        int j = ip[q];
        m = fmaxf(m, g_v[(size_t)(bbase + j) * FOUT + o]);
    }
    out[gid] = g_u[gid] + m;
}

// ---------------- launch ----------------
extern "C" void kernel_launch(void* const* d_in, const int* in_sizes, int n_in,
                              void* d_out, int out_size) {
    const float* x    = (const float*)d_in[0];
    const float* W    = (const float*)d_in[1];
    const float* bias = (const float*)d_in[2];
    // d_in[3] is k (constant 20, baked in)
    float* out = (float*)d_out;

    transform_kernel<<<TOTAL / 128, 128>>>(x, W, bias);
    dist_kernel<<<dim3(528, 1, BATCH), 256>>>(x);      // 528 = upper-tri 32x32 tiles
    select_kernel<<<TOTAL, 256>>>();
    gather_kernel<<<(TOTAL * FOUT) / 256, 256>>>(out);
}

// round 5
// speedup vs baseline: 1.1311x; 1.1311x over previous
#include <cuda_runtime.h>
#include <cstdint>

#define BATCH 4
#define NPTS  4096
#define FIN   64
#define FOUT  64
#define KNN   20
#define TOTAL (BATCH * NPTS)   // 16384 points

// ---------------- scratch (static device memory; no allocations) ----------------
__device__ float g_key[(size_t)TOTAL * NPTS];   // 268 MB ranking keys
__device__ float g_u[TOTAL * FOUT];             // (W1-W2)x + b
__device__ float g_v[TOTAL * FOUT];             // W2 x
__device__ float g_xs[TOTAL];                   // squared norms
__device__ int   g_idx[TOTAL * KNN];            // knn indices (local to batch)

// ---------------- kernel A: per-point transform ----------------
// u = (W1 - W2) x + b ; v = W2 x ; xs = ||x||^2
__global__ void transform_kernel(const float* __restrict__ x,
                                 const float* __restrict__ W,
                                 const float* __restrict__ bias) {
    __shared__ float Ws[FOUT * 2 * FIN];
    __shared__ float bs[FOUT];
    int t = threadIdx.x;
    for (int i = t; i < FOUT * 2 * FIN; i += blockDim.x) Ws[i] = W[i];
    if (t < FOUT) bs[t] = bias[t];
    __syncthreads();

    int p = blockIdx.x * blockDim.x + t;   // grid covers exactly TOTAL
    float xr[FIN];
    const float4* xp = (const float4*)(x + (size_t)p * FIN);
#pragma unroll
    for (int q = 0; q < FIN / 4; q++) {
        float4 v4 = xp[q];
        xr[4*q+0] = v4.x; xr[4*q+1] = v4.y; xr[4*q+2] = v4.z; xr[4*q+3] = v4.w;
    }
    float s = 0.f;
#pragma unroll
    for (int c = 0; c < FIN; c++) s += xr[c] * xr[c];
    g_xs[p] = s;

    for (int o = 0; o < FOUT; o++) {
        float a1 = 0.f, a2 = 0.f;
        const float* wrow = &Ws[o * 2 * FIN];
#pragma unroll
        for (int c = 0; c < FIN; c++) {
            a1 += xr[c] * wrow[c];
            a2 += xr[c] * wrow[FIN + c];
        }
        g_u[p * FOUT + o] = a1 - a2 + bs[o];
        g_v[p * FOUT + o] = a2;
    }
}

// ---------------- kernel B: symmetric Gram + ranking keys ----------------
// key[i][j] = xs[j] - 2*dot(x_i,x_j)   (same row-order as reference dist)
#define TILE 128
#define KCH  32
#define SSTR 132   // padded stride to dodge bank conflicts on transposed stores

// occupancy 1: full 255-reg budget, NO spills of the 64-reg accumulator tile.
__global__ __launch_bounds__(256, 1) void dist_kernel(const float* __restrict__ x) {
    __shared__ float As[KCH][SSTR];
    __shared__ float Bs[KCH][SSTR];
    int b = blockIdx.z;
    // map linear id -> upper-triangular (by, bx), bx >= by, 32x32 tile grid
    int id = blockIdx.x;
    int by = 0, rem = id;
    while (rem >= 32 - by) { rem -= 32 - by; by++; }
    int bx = by + rem;

    const float* X = x + (size_t)b * NPTS * FIN;
    int row0 = by * TILE, col0 = bx * TILE;
    int t  = threadIdx.x;
    int tr = t >> 4, tc = t & 15;          // 16 x 16 thread grid, 8x8 micro-tile

    float acc[8][8];
#pragma unroll
    for (int i = 0; i < 8; i++)
#pragma unroll
        for (int j = 0; j < 8; j++) acc[i][j] = 0.f;

    for (int kk = 0; kk < FIN; kk += KCH) {
        // load 128 rows x 32 f, transposed into f-major smem
        for (int q = t; q < TILE * KCH / 4; q += 256) {
            int r  = q >> 3;
            int fs = (q & 7) << 2;
            float4 va = *(const float4*)(X + (size_t)(row0 + r) * FIN + kk + fs);
            As[fs+0][r] = va.x; As[fs+1][r] = va.y; As[fs+2][r] = va.z; As[fs+3][r] = va.w;
            float4 vb = *(const float4*)(X + (size_t)(col0 + r) * FIN + kk + fs);
            Bs[fs+0][r] = vb.x; Bs[fs+1][r] = vb.y; Bs[fs+2][r] = vb.z; Bs[fs+3][r] = vb.w;
        }
        __syncthreads();
#pragma unroll
        for (int f = 0; f < KCH; f++) {
            float4 a0 = *(const float4*)&As[f][tr * 8];
            float4 a1 = *(const float4*)&As[f][tr * 8 + 4];
            float4 b0 = *(const float4*)&Bs[f][tc * 8];
            float4 b1 = *(const float4*)&Bs[f][tc * 8 + 4];
            float av[8] = {a0.x,a0.y,a0.z,a0.w,a1.x,a1.y,a1.z,a1.w};
            float bv[8] = {b0.x,b0.y,b0.z,b0.w,b1.x,b1.y,b1.z,b1.w};
#pragma unroll
            for (int i = 0; i < 8; i++)
#pragma unroll
                for (int j = 0; j < 8; j++) acc[i][j] = fmaf(av[i], bv[j], acc[i][j]);
        }
        __syncthreads();
    }

    float xsr[8], xsc[8];
#pragma unroll
    for (int i = 0; i < 8; i++) xsr[i] = g_xs[b * NPTS + row0 + tr * 8 + i];
#pragma unroll
    for (int j = 0; j < 8; j++) xsc[j] = g_xs[b * NPTS + col0 + tc * 8 + j];

    // direct block: key[row][col] = xs[col] - 2*acc   (streaming stores)
#pragma unroll
    for (int i = 0; i < 8; i++) {
        size_t base = (size_t)(b * NPTS + row0 + tr * 8 + i) * NPTS + col0 + tc * 8;
        float4 o0 = make_float4(xsc[0] - 2.f*acc[i][0], xsc[1] - 2.f*acc[i][1],
                                xsc[2] - 2.f*acc[i][2], xsc[3] - 2.f*acc[i][3]);
        float4 o1 = make_float4(xsc[4] - 2.f*acc[i][4], xsc[5] - 2.f*acc[i][5],
                                xsc[6] - 2.f*acc[i][6], xsc[7] - 2.f*acc[i][7]);
        __stcs((float4*)&g_key[base],     o0);
        __stcs((float4*)&g_key[base + 4], o1);
    }
    // mirrored block: key[col][row] = xs[row] - 2*acc  (diag tile already full)
    // each thread's 2 float4s are one contiguous 32B sector -> no sector waste
    if (bx != by) {
#pragma unroll
        for (int j = 0; j < 8; j++) {
            size_t base = (size_t)(b * NPTS + col0 + tc * 8 + j) * NPTS + row0 + tr * 8;
            float4 o0 = make_float4(xsr[0] - 2.f*acc[0][j], xsr[1] - 2.f*acc[1][j],
                                    xsr[2] - 2.f*acc[2][j], xsr[3] - 2.f*acc[3][j]);
            float4 o1 = make_float4(xsr[4] - 2.f*acc[4][j], xsr[5] - 2.f*acc[5][j],
                                    xsr[6] - 2.f*acc[6][j], xsr[7] - 2.f*acc[7][j]);
            __stcs((float4*)&g_key[base],     o0);
            __stcs((float4*)&g_key[base + 4], o1);
        }
    }
}

// ---------------- kernel C: per-row top-20 selection ----------------
// key packed as (ordered float bits << 32) | j  => lexicographic (dist, index),
// exactly matching stable argsort tie-breaks. Self (j==i) excluded.
// Two-phase: per-warp top-20 of 512 elems (no block sync), then warp 0 merges
// the 8*20=160 candidates. Only ONE __syncthreads total.
__global__ __launch_bounds__(256) void select_kernel() {
    int row = blockIdx.x;
    int iLocal = row & (NPTS - 1);
    const float4* keys = (const float4*)(g_key + (size_t)row * NPTS);
    int t = threadIdx.x;
    int lane = t & 31, wid = t >> 5;

    // warp `wid` owns j in [wid*512, wid*512+512); lane loads 4 float4s
    unsigned long long lk[16];
#pragma unroll
    for (int i = 0; i < 4; i++) {
        int f4 = wid * 128 + i * 32 + lane;       // coalesced float4 index
        float4 v = __ldcs(&keys[f4]);
        int j0 = f4 * 4;
        float vv[4] = {v.x, v.y, v.z, v.w};
#pragma unroll
        for (int e = 0; e < 4; e++) {
            unsigned u = __float_as_uint(vv[e]);
            u = (u & 0x80000000u) ? ~u : (u | 0x80000000u);
            unsigned long long key = ((unsigned long long)u << 32) | (unsigned)(j0 + e);
            lk[i * 4 + e] = (j0 + e == iLocal) ? ~0ULL : key;
        }
    }

    __shared__ unsigned long long cand[8 * KNN];

    // phase 1: each warp extracts its top-KNN (ascending) via butterfly min
    for (int sel = 0; sel < KNN; sel++) {
        unsigned long long m = ~0ULL;
#pragma unroll
        for (int q = 0; q < 16; q++) m = (lk[q] < m) ? lk[q] : m;
        unsigned long long r = m;
#pragma unroll
        for (int off = 16; off; off >>= 1) {
            unsigned long long o = __shfl_xor_sync(0xffffffffu, r, off);
            r = (o < r) ? o : r;
        }
        if (lane == 0) cand[wid * KNN + sel] = r;
#pragma unroll
        for (int q = 0; q < 16; q++) if (lk[q] == r) lk[q] = ~0ULL;  // unique owner
    }
    __syncthreads();

    // phase 2: warp 0 merges 160 candidates (5 per lane)
    if (wid == 0) {
        unsigned long long c[5];
#pragma unroll
        for (int i = 0; i < 5; i++) c[i] = cand[i * 32 + lane];
        for (int sel = 0; sel < KNN; sel++) {
            unsigned long long m = ~0ULL;
#pragma unroll
            for (int i = 0; i < 5; i++) m = (c[i] < m) ? c[i] : m;
            unsigned long long r = m;
#pragma unroll
            for (int off = 16; off; off >>= 1) {
                unsigned long long o = __shfl_xor_sync(0xffffffffu, r, off);
                r = (o < r) ? o : r;
            }
            if (lane == 0) g_idx[row * KNN + sel] = (int)(r & 0xffffffffu);
#pragma unroll
            for (int i = 0; i < 5; i++) if (c[i] == r) c[i] = ~0ULL;
        }
    }
}

// ---------------- kernel D: gather-max epilogue ----------------
__global__ void gather_kernel(float* __restrict__ out) {
    int gid = blockIdx.x * blockDim.x + threadIdx.x;   // TOTAL*FOUT threads
    int p = gid >> 6;
    int o = gid & 63;
    int bbase = p & ~(NPTS - 1);
    const int* ip = g_idx + p * KNN;
    float m = -3.402823466e38f;
#pragma unroll
    for (int q = 0; q < KNN; q++) {
        int j = ip[q];
        m = fmaxf(m, g_v[(size_t)(bbase + j) * FOUT + o]);
    }
    out[gid] = g_u[gid] + m;
}

// ---------------- launch ----------------
extern "C" void kernel_launch(void* const* d_in, const int* in_sizes, int n_in,
                              void* d_out, int out_size) {
    const float* x    = (const float*)d_in[0];
    const float* W    = (const float*)d_in[1];
    const float* bias = (const float*)d_in[2];
    // d_in[3] is k (constant 20, baked in)
    float* out = (float*)d_out;

    transform_kernel<<<TOTAL / 128, 128>>>(x, W, bias);
    dist_kernel<<<dim3(528, 1, BATCH), 256>>>(x);      // 528 = upper-tri 32x32 tiles
    select_kernel<<<TOTAL, 256>>>();
    gather_kernel<<<(TOTAL * FOUT) / 256, 256>>>(out);
}

// round 7
// speedup vs baseline: 2.3312x; 2.0610x over previous
#include <cuda_runtime.h>
#include <cstdint>

#define BATCH 4
#define NPTS  4096
#define FIN   64
#define FOUT  64
#define KNN   20
#define TOTAL (BATCH * NPTS)   // 16384 points

// ---------------- scratch (static device memory; no allocations) ----------------
__device__ float g_key[(size_t)TOTAL * NPTS];   // 268 MB ranking keys
__device__ float g_u[TOTAL * FOUT];             // (W1-W2)x + b
__device__ float g_v[TOTAL * FOUT];             // W2 x
__device__ float g_xs[TOTAL];                   // squared norms
__device__ int   g_idx[TOTAL * KNN];            // knn indices (local to batch)

// ---------------- kernel A: per-point transform ----------------
__global__ void transform_kernel(const float* __restrict__ x,
                                 const float* __restrict__ W,
                                 const float* __restrict__ bias) {
    __shared__ float Ws[FOUT * 2 * FIN];
    __shared__ float bs[FOUT];
    int t = threadIdx.x;
    for (int i = t; i < FOUT * 2 * FIN; i += blockDim.x) Ws[i] = W[i];
    if (t < FOUT) bs[t] = bias[t];
    __syncthreads();

    int p = blockIdx.x * blockDim.x + t;
    float xr[FIN];
    const float4* xp = (const float4*)(x + (size_t)p * FIN);
#pragma unroll
    for (int q = 0; q < FIN / 4; q++) {
        float4 v4 = xp[q];
        xr[4*q+0] = v4.x; xr[4*q+1] = v4.y; xr[4*q+2] = v4.z; xr[4*q+3] = v4.w;
    }
    float s = 0.f;
#pragma unroll
    for (int c = 0; c < FIN; c++) s += xr[c] * xr[c];
    g_xs[p] = s;

    for (int o = 0; o < FOUT; o++) {
        float a1 = 0.f, a2 = 0.f;
        const float* wrow = &Ws[o * 2 * FIN];
#pragma unroll
        for (int c = 0; c < FIN; c++) {
            a1 += xr[c] * wrow[c];
            a2 += xr[c] * wrow[FIN + c];
        }
        g_u[p * FOUT + o] = a1 - a2 + bs[o];
        g_v[p * FOUT + o] = a2;
    }
}

// ---------------- kernel B: symmetric Gram + ranking keys (unchanged) ----------------
#define TILE 128
#define KCH  32
#define SSTR 132

__global__ __launch_bounds__(256, 1) void dist_kernel(const float* __restrict__ x) {
    __shared__ float As[KCH][SSTR];
    __shared__ float Bs[KCH][SSTR];
    int b = blockIdx.z;
    int id = blockIdx.x;
    int by = 0, rem = id;
    while (rem >= 32 - by) { rem -= 32 - by; by++; }
    int bx = by + rem;

    const float* X = x + (size_t)b * NPTS * FIN;
    int row0 = by * TILE, col0 = bx * TILE;
    int t  = threadIdx.x;
    int tr = t >> 4, tc = t & 15;

    float acc[8][8];
#pragma unroll
    for (int i = 0; i < 8; i++)
#pragma unroll
        for (int j = 0; j < 8; j++) acc[i][j] = 0.f;

    for (int kk = 0; kk < FIN; kk += KCH) {
        for (int q = t; q < TILE * KCH / 4; q += 256) {
            int r  = q >> 3;
            int fs = (q & 7) << 2;
            float4 va = *(const float4*)(X + (size_t)(row0 + r) * FIN + kk + fs);
            As[fs+0][r] = va.x; As[fs+1][r] = va.y; As[fs+2][r] = va.z; As[fs+3][r] = va.w;
            float4 vb = *(const float4*)(X + (size_t)(col0 + r) * FIN + kk + fs);
            Bs[fs+0][r] = vb.x; Bs[fs+1][r] = vb.y; Bs[fs+2][r] = vb.z; Bs[fs+3][r] = vb.w;
        }
        __syncthreads();
#pragma unroll
        for (int f = 0; f < KCH; f++) {
            float4 a0 = *(const float4*)&As[f][tr * 8];
            float4 a1 = *(const float4*)&As[f][tr * 8 + 4];
            float4 b0 = *(const float4*)&Bs[f][tc * 8];
            float4 b1 = *(const float4*)&Bs[f][tc * 8 + 4];
            float av[8] = {a0.x,a0.y,a0.z,a0.w,a1.x,a1.y,a1.z,a1.w};
            float bv[8] = {b0.x,b0.y,b0.z,b0.w,b1.x,b1.y,b1.z,b1.w};
#pragma unroll
            for (int i = 0; i < 8; i++)
#pragma unroll
                for (int j = 0; j < 8; j++) acc[i][j] = fmaf(av[i], bv[j], acc[i][j]);
        }
        __syncthreads();
    }

    float xsr[8], xsc[8];
#pragma unroll
    for (int i = 0; i < 8; i++) xsr[i] = g_xs[b * NPTS + row0 + tr * 8 + i];
#pragma unroll
    for (int j = 0; j < 8; j++) xsc[j] = g_xs[b * NPTS + col0 + tc * 8 + j];

#pragma unroll
    for (int i = 0; i < 8; i++) {
        size_t base = (size_t)(b * NPTS + row0 + tr * 8 + i) * NPTS + col0 + tc * 8;
        float4 o0 = make_float4(xsc[0] - 2.f*acc[i][0], xsc[1] - 2.f*acc[i][1],
                                xsc[2] - 2.f*acc[i][2], xsc[3] - 2.f*acc[i][3]);
        float4 o1 = make_float4(xsc[4] - 2.f*acc[i][4], xsc[5] - 2.f*acc[i][5],
                                xsc[6] - 2.f*acc[i][6], xsc[7] - 2.f*acc[i][7]);
        __stcs((float4*)&g_key[base],     o0);
        __stcs((float4*)&g_key[base + 4], o1);
    }
    if (bx != by) {
#pragma unroll
        for (int j = 0; j < 8; j++) {
            size_t base = (size_t)(b * NPTS + col0 + tc * 8 + j) * NPTS + row0 + tr * 8;
            float4 o0 = make_float4(xsr[0] - 2.f*acc[0][j], xsr[1] - 2.f*acc[1][j],
                                    xsr[2] - 2.f*acc[2][j], xsr[3] - 2.f*acc[3][j]);
            float4 o1 = make_float4(xsr[4] - 2.f*acc[4][j], xsr[5] - 2.f*acc[5][j],
                                    xsr[6] - 2.f*acc[6][j], xsr[7] - 2.f*acc[7][j]);
            __stcs((float4*)&g_key[base],     o0);
            __stcs((float4*)&g_key[base + 4], o1);
        }
    }
}

// ---------------- kernel C: radix top-20 selection ----------------
// MSB-first 4x8-bit radix select over ordered float bits, keys in registers.
// Finds exact value theta of the 20th-smallest and the tie rank; the output
// SET (not order) must match stable argsort: all keys < theta, plus the
// smallest-index keys == theta. Order of g_idx is irrelevant (max over set).
__global__ __launch_bounds__(256) void select_kernel() {
    int row = blockIdx.x;
    int iLocal = row & (NPTS - 1);
    const float4* keys = (const float4*)(g_key + (size_t)row * NPTS);
    int t = threadIdx.x;

    // 16 keys per thread; thread t holds j = (t + i*256)*4 + e  (coalesced f4)
    unsigned v[16];
#pragma unroll
    for (int i2 = 0; i2 < 4; i2++) {
        int f4 = t + i2 * 256;
        float4 kv = __ldcs(&keys[f4]);
        float vv[4] = {kv.x, kv.y, kv.z, kv.w};
        int j0 = f4 * 4;
#pragma unroll
        for (int e = 0; e < 4; e++) {
            unsigned u = __float_as_uint(vv[e]);
            u = (u & 0x80000000u) ? ~u : (u | 0x80000000u);
            v[i2 * 4 + e] = (j0 + e == iLocal) ? 0xFFFFFFFFu : u;  // exclude self
        }
    }

    __shared__ int hist[256];
    __shared__ int sD, sCb, sNeed;
    __shared__ int cnt1, cntT, chosen;
    __shared__ int tieb[64];
    __shared__ int wred[8];

    unsigned prefix = 0, pmask = 0;
    if (t == 0) sNeed = KNN;

    for (int pass = 0; pass < 4; pass++) {
        int shift = 24 - 8 * pass;
        hist[t] = 0;
        __syncthreads();
#pragma unroll
        for (int q = 0; q < 16; q++) {
            bool ok = (v[q] & pmask) == prefix;
            unsigned act = __ballot_sync(0xffffffffu, ok);
            if (ok) {
                unsigned d = (v[q] >> shift) & 255u;
                unsigned m = __match_any_sync(act, d);   // aggregate same-bin lanes
                if ((t & 31) == (__ffs(m) - 1))
                    atomicAdd(&hist[d], __popc(m));
            }
        }
        __syncthreads();
        if (t < 32) {  // warp 0: find crossing digit
            int s[8], tot = 0, base = t * 8;
#pragma unroll
            for (int q2 = 0; q2 < 8; q2++) { s[q2] = hist[base + q2]; tot += s[q2]; }
            int inc = tot;
#pragma unroll
            for (int off = 1; off < 32; off <<= 1) {
                int o = __shfl_up_sync(0xffffffffu, inc, off);
                if (t >= off) inc += o;
            }
            int ex = inc - tot;
            int nd = sNeed;
            if (ex < nd && nd <= inc) {   // exactly one lane crosses
                int run = ex;
#pragma unroll
                for (int q2 = 0; q2 < 8; q2++) {
                    if (nd <= run + s[q2]) { sD = base + q2; sCb = run; break; }
                    run += s[q2];
                }
            }
        }
        __syncthreads();
        prefix |= ((unsigned)sD) << shift;
        pmask  |= 0xFFu << shift;
        if (t == 0) sNeed -= sCb;   // visible via next pass's hist-zero sync
    }

    // collect
    if (t == 0) { cnt1 = 0; cntT = 0; }
    __syncthreads();
    unsigned theta = prefix;
    int* outp = g_idx + row * KNN;
#pragma unroll
    for (int q = 0; q < 16; q++) {
        int j = (t + (q >> 2) * 256) * 4 + (q & 3);
        if (v[q] < theta)       { int s2 = atomicAdd(&cnt1, 1); outp[s2] = j; }
        else if (v[q] == theta) { int s2 = atomicAdd(&cntT, 1); if (s2 < 64) tieb[s2] = j; }
    }
    __syncthreads();
    int needF = sNeed;   // ties to take (>=1); cnt1 == KNN - needF by construction
    if (cntT <= 64) {
        if (t == 0) {    // typically cntT==1: trivial
            int c1 = cnt1, nt = cntT;
            for (int s2 = 0; s2 < needF; s2++) {
                int bi = 0, bv = 0x7fffffff;
                for (int q = 0; q < nt; q++) if (tieb[q] < bv) { bv = tieb[q]; bi = q; }
                tieb[bi] = 0x7fffffff;
                outp[c1 + s2] = bv;
            }
        }
    } else {
        // pathological massive tie: block-reduce needF smallest tie indices
        unsigned used = 0;
        for (int s2 = 0; s2 < needF; s2++) {
            int lm = 0x7fffffff;
#pragma unroll
            for (int q = 0; q < 16; q++) {
                int j = (t + (q >> 2) * 256) * 4 + (q & 3);
                if (v[q] == theta && !(used & (1u << q)) && j < lm) lm = j;
            }
            int r = lm;
#pragma unroll
            for (int off = 16; off; off >>= 1)
                r = min(r, __shfl_xor_sync(0xffffffffu, r, off));
            if ((t & 31) == 0) wred[t >> 5] = r;
            __syncthreads();
            if (t == 0) {
                int bm = 0x7fffffff;
                for (int w = 0; w < 8; w++) bm = min(bm, wred[w]);
                chosen = bm;
                outp[cnt1 + s2] = bm;
            }
            __syncthreads();
            int cj = chosen;
#pragma unroll
            for (int q = 0; q < 16; q++) {
                int j = (t + (q >> 2) * 256) * 4 + (q & 3);
                if (j == cj) used |= (1u << q);
            }
        }
    }
}

// ---------------- kernel D: gather-max epilogue ----------------
__global__ void gather_kernel(float* __restrict__ out) {
    int gid = blockIdx.x * blockDim.x + threadIdx.x;
    int p = gid >> 6;
    int o = gid & 63;
    int bbase = p & ~(NPTS - 1);
    const int* ip = g_idx + p * KNN;
    float m = -3.402823466e38f;
#pragma unroll
    for (int q = 0; q < KNN; q++) {
        int j = ip[q];
        m = fmaxf(m, g_v[(size_t)(bbase + j) * FOUT + o]);
    }
    out[gid] = g_u[gid] + m;
}

// ---------------- launch ----------------
extern "C" void kernel_launch(void* const* d_in, const int* in_sizes, int n_in,
                              void* d_out, int out_size) {
    const float* x    = (const float*)d_in[0];
    const float* W    = (const float*)d_in[1];
    const float* bias = (const float*)d_in[2];
    float* out = (float*)d_out;

    transform_kernel<<<TOTAL / 128, 128>>>(x, W, bias);
    dist_kernel<<<dim3(528, 1, BATCH), 256>>>(x);
    select_kernel<<<TOTAL, 256>>>();
    gather_kernel<<<(TOTAL * FOUT) / 256, 256>>>(out);
}